// round 15
// baseline (speedup 1.0000x reference)
#include <cuda_runtime.h>
#include <math.h>
#include <stdint.h>

// Problem constants (fixed by the reference)
#define HEAD_SIZE  128
#define HALF_ROT   64
#define NUM_TOKENS 8192
#define NUM_HEADS  32
#define ROW        6144          // (32 + 2*8) * 128
#define V_OFF      5120          // (32+8)*128 ; V slice = 1024 floats/token
#define EPS        1e-6f

// L2::evict_last policy, created ONCE per thread (R14 re-created it inside
// every volatile asm block, which also froze load scheduling).
__device__ __forceinline__ uint64_t mkpol() {
    uint64_t pol;
    asm("createpolicy.fractional.L2::evict_last.b64 %0, 1.0;" : "=l"(pol));
    return pol;
}

// 256-bit policy-hinted load — NOT volatile: pure, lets ptxas batch/reorder.
__device__ __forceinline__ void ldg256(const float* p, uint64_t pol, float v[8]) {
    uint32_t a,b,c,d,e,f,g,h;
    asm("ld.global.nc.L2::cache_hint.v8.b32 {%0,%1,%2,%3,%4,%5,%6,%7}, [%8], %9;"
        : "=r"(a),"=r"(b),"=r"(c),"=r"(d),"=r"(e),"=r"(f),"=r"(g),"=r"(h)
        : "l"(p), "l"(pol));
    v[0]=__uint_as_float(a); v[1]=__uint_as_float(b);
    v[2]=__uint_as_float(c); v[3]=__uint_as_float(d);
    v[4]=__uint_as_float(e); v[5]=__uint_as_float(f);
    v[6]=__uint_as_float(g); v[7]=__uint_as_float(h);
}

// 256-bit policy-hinted store.
__device__ __forceinline__ void stg256(float* p, uint64_t pol, const float v[8]) {
    asm volatile(
        "st.global.L2::cache_hint.v8.b32 [%0], {%1,%2,%3,%4,%5,%6,%7,%8}, %9;"
        :: "l"(p),
           "r"(__float_as_uint(v[0])), "r"(__float_as_uint(v[1])),
           "r"(__float_as_uint(v[2])), "r"(__float_as_uint(v[3])),
           "r"(__float_as_uint(v[4])), "r"(__float_as_uint(v[5])),
           "r"(__float_as_uint(v[6])), "r"(__float_as_uint(v[7])),
           "l"(pol)
        : "memory");
}

// 2 tokens/block; warp w -> token w>>2, heads 10*(w&3)..+9.
// Each 256-bit access covers a PAIR of adjacent heads: lanes 0-15 = head 2i,
// lanes 16-31 = head 2i+1; sub-lane s (=lane&15) holds dims 8s..8s+7.
__global__ __launch_bounds__(256, 2)
void rope_qknorm_kernel(const float* __restrict__ qkv,
                        const float* __restrict__ qw,
                        const float* __restrict__ kw,
                        const int*   __restrict__ pos,
                        float*       __restrict__ out)
{
    __shared__ float s_cos[2][HALF_ROT];
    __shared__ float s_sin[2][HALF_ROT];

    const int tid  = threadIdx.x;
    const int lane = tid & 31;
    const int warp = tid >> 5;
    const int s    = lane & 15;               // sub-lane within head group

    const uint64_t pol = mkpol();

    const int t0 = 2 * blockIdx.x;            // tokens t0, t0+1
    const float* row0  = qkv + (size_t)t0 * ROW;
    float*       orow0 = out + (size_t)t0 * ROW;

    // pos loads first (gate the trig chain)
    int p = 0;
    if (tid < 128) p = pos[t0 + (tid >> 6)];  // threads 0-63: t0, 64-127: t0+1

    // V passthrough: 2048 floats / 256 threads * 8 — one v8 ld+st each
    const int vt  = tid >> 7;                  // token
    const int idx = tid & 127;
    float v[8];
    ldg256(row0 + (size_t)vt * ROW + V_OFF + idx * 8, pol, v);

    // batch all 5 head-pair loads (10 heads per warp)
    const int  wtk = warp >> 2;                // warp's token (0 or 1)
    const int  hb  = 10 * (warp & 3);          // first head of this warp
    const float* wrow = row0 + (size_t)wtk * ROW;
    float*       wout = orow0 + (size_t)wtk * ROW;

    float y[5][8];
    #pragma unroll
    for (int i = 0; i < 5; i++)
        ldg256(wrow + (hb + 2 * i) * HEAD_SIZE + lane * 8, pol, y[i]);

    stg256(orow0 + (size_t)vt * ROW + V_OFF + idx * 8, pol, v);

    // weights for this lane's 8 dims (both q and k variants)
    float wq8[8], wk8[8];
    *(float4*)(wq8)     = ((const float4*)qw)[2 * s];
    *(float4*)(wq8 + 4) = ((const float4*)qw)[2 * s + 1];
    *(float4*)(wk8)     = ((const float4*)kw)[2 * s];
    *(float4*)(wk8 + 4) = ((const float4*)kw)[2 * s + 1];

    // cos/sin tables: threads 0-63 -> token0, 64-127 -> token1
    // inv_freq[d] = 10000^(-d/64); double exp for correctly rounded fp32
    // (c = ln(10000)/64 = 0.14391156831212787). Overlaps in-flight LDGs.
    if (tid < 128) {
        const int d = tid & 63;
        const double c = 0.14391156831212787;
        const float invf = (float)exp(-c * (double)d);
        float ang = (float)p * invf;           // fp32 product = reference rounding
        float sv, cv;
        sincosf(ang, &sv, &cv);
        s_cos[tid >> 6][d] = cv;
        s_sin[tid >> 6][d] = sv;
    }

    // rmsnorm: reduce over the 16-lane head group (128 elems = 16 lanes * 8)
    const int g = lane >> 4;                   // which head of the pair
    #pragma unroll
    for (int i = 0; i < 5; i++) {
        const int h = hb + 2 * i + g;          // 0..39
        float ss = 0.f;
        #pragma unroll
        for (int j = 0; j < 8; j++) ss += y[i][j] * y[i][j];
        #pragma unroll
        for (int o = 8; o; o >>= 1)            // xor <= 8 stays within group
            ss += __shfl_xor_sync(0xffffffffu, ss, o);

        const float inv = rsqrtf(ss * (1.0f / 128.0f) + EPS);
        const float* w = (h < NUM_HEADS) ? wq8 : wk8;
        #pragma unroll
        for (int j = 0; j < 8; j++) y[i][j] *= inv * w[j];
    }

    __syncthreads();

    // per-lane rope invariants: sub-lane s holds dims 8s..8s+7
    const int   cb  = 8 * (s & 7);             // cos/sin base index
    const float sgn = (s < 8) ? -1.0f : 1.0f;  // x1*c - x2*s | x2*c + x1*s
    float cs[8], sn[8];
    *(float4*)(cs)     = *(const float4*)(&s_cos[wtk][cb]);
    *(float4*)(cs + 4) = *(const float4*)(&s_cos[wtk][cb + 4]);
    *(float4*)(sn)     = *(const float4*)(&s_sin[wtk][cb]);
    *(float4*)(sn + 4) = *(const float4*)(&s_sin[wtk][cb + 4]);

    // rope + 256-bit store
    #pragma unroll
    for (int i = 0; i < 5; i++) {
        float r[8];
        #pragma unroll
        for (int j = 0; j < 8; j++) {
            // partner dim d <-> d+64 lives exactly 8 lanes away (same group)
            float pr = __shfl_xor_sync(0xffffffffu, y[i][j], 8);
            r[j] = fmaf(sgn * pr, sn[j], y[i][j] * cs[j]);
        }
        stg256(wout + (hb + 2 * i) * HEAD_SIZE + lane * 8, pol, r);
    }
}

extern "C" void kernel_launch(void* const* d_in, const int* in_sizes, int n_in,
                              void* d_out, int out_size) {
    const float* qkv = (const float*)d_in[0];
    const float* qw  = (const float*)d_in[1];
    const float* kw  = (const float*)d_in[2];
    const int*   pos = (const int*)d_in[3];
    float* out = (float*)d_out;

    rope_qknorm_kernel<<<NUM_TOKENS / 2, 256>>>(qkv, qw, kw, pos, out);
}

// round 16
// speedup vs baseline: 1.0468x; 1.0468x over previous
#include <cuda_runtime.h>
#include <math.h>
#include <stdint.h>

// Problem constants (fixed by the reference)
#define HEAD_SIZE  128
#define HALF_ROT   64
#define NUM_TOKENS 8192
#define NUM_HEADS  32
#define ROW        6144          // (32 + 2*8) * 128
#define V_OFF      5120          // (32+8)*128 ; V slice = 1024 floats/token
#define EPS        1e-6f

// 256-bit global load, L2::evict_last policy (createpolicy+cache_hint form —
// width-unrestricted; the evict_last policy measured +7% BW in R11/R12).
// NOTE (R15 lesson): the volatile asm blocks with inline createpolicy are
// load-bearing — they pin the front-batched issue order of the memory phase.
// Hoisting the policy / dropping volatile let ptxas reorder and cost 3.5 us.
__device__ __forceinline__ void ldg256(const float* p, float v[8]) {
    uint32_t a,b,c,d,e,f,g,h;
    asm volatile(
        "{\n\t"
        ".reg .b64 pol;\n\t"
        "createpolicy.fractional.L2::evict_last.b64 pol, 1.0;\n\t"
        "ld.global.nc.L2::cache_hint.v8.b32 {%0,%1,%2,%3,%4,%5,%6,%7}, [%8], pol;\n\t"
        "}"
        : "=r"(a),"=r"(b),"=r"(c),"=r"(d),"=r"(e),"=r"(f),"=r"(g),"=r"(h)
        : "l"(p));
    v[0]=__uint_as_float(a); v[1]=__uint_as_float(b);
    v[2]=__uint_as_float(c); v[3]=__uint_as_float(d);
    v[4]=__uint_as_float(e); v[5]=__uint_as_float(f);
    v[6]=__uint_as_float(g); v[7]=__uint_as_float(h);
}

// 256-bit global store, same evict_last policy.
__device__ __forceinline__ void stg256(float* p, const float v[8]) {
    asm volatile(
        "{\n\t"
        ".reg .b64 pol;\n\t"
        "createpolicy.fractional.L2::evict_last.b64 pol, 1.0;\n\t"
        "st.global.L2::cache_hint.v8.b32 [%0], {%1,%2,%3,%4,%5,%6,%7,%8}, pol;\n\t"
        "}"
        :: "l"(p),
           "r"(__float_as_uint(v[0])), "r"(__float_as_uint(v[1])),
           "r"(__float_as_uint(v[2])), "r"(__float_as_uint(v[3])),
           "r"(__float_as_uint(v[4])), "r"(__float_as_uint(v[5])),
           "r"(__float_as_uint(v[6])), "r"(__float_as_uint(v[7]))
        : "memory");
}

// 2 tokens/block; warp w -> token w>>2, heads 10*(w&3)..+9.
// Each 256-bit access covers a PAIR of adjacent heads: lanes 0-15 = head 2i,
// lanes 16-31 = head 2i+1; sub-lane s (=lane&15) holds dims 8s..8s+7.
__global__ __launch_bounds__(256, 2)
void rope_qknorm_kernel(const float* __restrict__ qkv,
                        const float* __restrict__ qw,
                        const float* __restrict__ kw,
                        const int*   __restrict__ pos,
                        float*       __restrict__ out)
{
    __shared__ float s_cos[2][HALF_ROT];
    __shared__ float s_sin[2][HALF_ROT];

    const int tid  = threadIdx.x;
    const int lane = tid & 31;
    const int warp = tid >> 5;
    const int s    = lane & 15;               // sub-lane within head group

    const int t0 = 2 * blockIdx.x;            // tokens t0, t0+1
    const float* row0  = qkv + (size_t)t0 * ROW;
    float*       orow0 = out + (size_t)t0 * ROW;

    // pos loads first (gate the trig chain)
    int p = 0;
    if (tid < 128) p = pos[t0 + (tid >> 6)];  // threads 0-63: t0, 64-127: t0+1

    // V passthrough: 2048 floats / 256 threads * 8 — one v8 ld+st each
    {
        const int vt  = tid >> 7;              // token
        const int idx = tid & 127;
        float v[8];
        ldg256(row0 + (size_t)vt * ROW + V_OFF + idx * 8, v);
        stg256(orow0 + (size_t)vt * ROW + V_OFF + idx * 8, v);
    }

    // batch all 5 head-pair loads (10 heads per warp) before the barrier
    const int  wtk = warp >> 2;                // warp's token (0 or 1)
    const int  hb  = 10 * (warp & 3);          // first head of this warp
    const float* wrow = row0 + (size_t)wtk * ROW;
    float*       wout = orow0 + (size_t)wtk * ROW;

    float y[5][8];
    #pragma unroll
    for (int i = 0; i < 5; i++)
        ldg256(wrow + (hb + 2 * i) * HEAD_SIZE + lane * 8, y[i]);

    // weights for this lane's 8 dims (both q and k variants)
    float wq8[8], wk8[8];
    *(float4*)(wq8)     = ((const float4*)qw)[2 * s];
    *(float4*)(wq8 + 4) = ((const float4*)qw)[2 * s + 1];
    *(float4*)(wk8)     = ((const float4*)kw)[2 * s];
    *(float4*)(wk8 + 4) = ((const float4*)kw)[2 * s + 1];

    // cos/sin tables: threads 0-63 -> token0, 64-127 -> token1
    // inv_freq[d] = 10000^(-d/64); double exp for correctly rounded fp32
    // (c = ln(10000)/64 = 0.14391156831212787). Overlaps in-flight LDGs.
    if (tid < 128) {
        const int d = tid & 63;
        const double c = 0.14391156831212787;
        const float invf = (float)exp(-c * (double)d);
        float ang = (float)p * invf;           // fp32 product = reference rounding
        float sv, cv;
        sincosf(ang, &sv, &cv);
        s_cos[tid >> 6][d] = cv;
        s_sin[tid >> 6][d] = sv;
    }

    // rmsnorm: reduce over the 16-lane head group (128 elems = 16 lanes * 8)
    const int g = lane >> 4;                   // which head of the pair
    #pragma unroll
    for (int i = 0; i < 5; i++) {
        const int h = hb + 2 * i + g;          // 0..39
        float ss = 0.f;
        #pragma unroll
        for (int j = 0; j < 8; j++) ss += y[i][j] * y[i][j];
        #pragma unroll
        for (int o = 8; o; o >>= 1)            // xor <= 8 stays within group
            ss += __shfl_xor_sync(0xffffffffu, ss, o);

        const float inv = rsqrtf(ss * (1.0f / 128.0f) + EPS);
        const float* w = (h < NUM_HEADS) ? wq8 : wk8;
        #pragma unroll
        for (int j = 0; j < 8; j++) y[i][j] *= inv * w[j];
    }

    __syncthreads();

    // per-lane rope invariants: sub-lane s holds dims 8s..8s+7
    const int   cb  = 8 * (s & 7);             // cos/sin base index
    const float sgn = (s < 8) ? -1.0f : 1.0f;  // x1*c - x2*s | x2*c + x1*s
    float cs[8], sn[8];
    *(float4*)(cs)     = *(const float4*)(&s_cos[wtk][cb]);
    *(float4*)(cs + 4) = *(const float4*)(&s_cos[wtk][cb + 4]);
    *(float4*)(sn)     = *(const float4*)(&s_sin[wtk][cb]);
    *(float4*)(sn + 4) = *(const float4*)(&s_sin[wtk][cb + 4]);

    // rope + 256-bit store
    #pragma unroll
    for (int i = 0; i < 5; i++) {
        float r[8];
        #pragma unroll
        for (int j = 0; j < 8; j++) {
            // partner dim d <-> d+64 lives exactly 8 lanes away (same group)
            float pr = __shfl_xor_sync(0xffffffffu, y[i][j], 8);
            r[j] = fmaf(sgn * pr, sn[j], y[i][j] * cs[j]);
        }
        stg256(wout + (hb + 2 * i) * HEAD_SIZE + lane * 8, r);
    }
}

extern "C" void kernel_launch(void* const* d_in, const int* in_sizes, int n_in,
                              void* d_out, int out_size) {
    const float* qkv = (const float*)d_in[0];
    const float* qw  = (const float*)d_in[1];
    const float* kw  = (const float*)d_in[2];
    const int*   pos = (const int*)d_in[3];
    float* out = (float*)d_out;

    rope_qknorm_kernel<<<NUM_TOKENS / 2, 256>>>(qkv, qw, kw, pos, out);
}